// round 8
// baseline (speedup 1.0000x reference)
#include <cuda_runtime.h>
#include <math.h>

#define NN   100000
#define EE   3200000
#define FIN  256
#define HID  16
#define CC   40
#define FULLM 0xffffffffu

#define SCAN_T 512
#define SCAN_B ((NN + SCAN_T - 1) / SCAN_T)   // 196

// ---------------- scratch (device globals; no allocation allowed) ------------
__device__ int      g_rowptr[NN + 1];
__device__ int      g_fill[NN];
__device__ int      g_rank[EE];
__device__ int      g_col[EE];
__device__ float    g_dinv[NN];
__device__ float4   g_f1[NN * 4];   // dinv * (x @ W1), 16 floats/node
__device__ float4   g_f2[NN * 4];   // dinv * relu(h1), 16 floats/node
__device__ unsigned g_flags[SCAN_B];  // decoupled-lookback state: (val<<2)|st

#define FFMA2(d, a, b) asm("fma.rn.f32x2 %0, %1, %2, %0;" : "+l"(d) : "l"(a), "l"(b))
#define FADD2(d, a, b) asm("add.rn.f32x2 %0, %1, %2;" : "=l"(d) : "l"(a), "l"(b))
#define PACK2(d, f)    asm("mov.b64 %0, {%1, %1};" : "=l"(d) : "f"(f))
#define UNPACK2(lo, hi, v) asm("mov.b64 {%0, %1}, %2;" : "=f"(lo), "=f"(hi) : "l"(v))

// ---------------- CSR build -------------------------------------------------
__global__ void k_zero() {
    int i = blockIdx.x * blockDim.x + threadIdx.x;
    if (i < NN) g_fill[i] = 0;
    if (i < SCAN_B) g_flags[i] = 0u;
}

// histogram + per-edge within-bucket rank (atomic return value)
__global__ void k_hist(const int* __restrict__ ei) {
    int i = blockIdx.x * blockDim.x + threadIdx.x;
    if (i < EE / 4) {
        int4 d = ((const int4*)(ei + EE))[i];
        int4 r;
        r.x = atomicAdd(&g_fill[d.x], 1);
        r.y = atomicAdd(&g_fill[d.y], 1);
        r.z = atomicAdd(&g_fill[d.z], 1);
        r.w = atomicAdd(&g_fill[d.w], 1);
        ((int4*)g_rank)[i] = r;
    }
}

// single-pass exclusive scan of g_fill -> g_rowptr, plus dinv. Decoupled lookback.
__global__ void k_scan() {
    __shared__ int wt[SCAN_T / 32];
    __shared__ int s_prefix;
    int tid = threadIdx.x, lane = tid & 31, wid = tid >> 5, b = blockIdx.x;
    int i = b * SCAN_T + tid;
    int v = (i < NN) ? g_fill[i] : 0;

    int x = v;
    #pragma unroll
    for (int off = 1; off < 32; off <<= 1) {
        int t = __shfl_up_sync(FULLM, x, off);
        if (lane >= off) x += t;
    }
    if (lane == 31) wt[wid] = x;
    __syncthreads();
    if (wid == 0) {
        int w = (lane < SCAN_T / 32) ? wt[lane] : 0;
        #pragma unroll
        for (int off = 1; off < SCAN_T / 32; off <<= 1) {
            int t = __shfl_up_sync(FULLM, w, off);
            if (lane >= off) w += t;
        }
        if (lane < SCAN_T / 32) wt[lane] = w;
    }
    __syncthreads();
    int block_tot = wt[SCAN_T / 32 - 1];
    int incl = ((wid == 0) ? 0 : wt[wid - 1]) + x;

    if (tid == 0) {
        unsigned pub = (b == 0) ? (((unsigned)block_tot << 2) | 2u)
                                : (((unsigned)block_tot << 2) | 1u);
        atomicExch(&g_flags[b], pub);
    }

    if (b == 0) {
        if (tid == 0) s_prefix = 0;
    } else if (wid == 0) {
        int prefix = 0;
        int base = b - 1;
        while (true) {
            int idx = base - lane;
            unsigned w = (idx >= 0) ? *((volatile unsigned*)&g_flags[idx]) : 2u;
            unsigned st = w & 3u;
            unsigned pm = __ballot_sync(FULLM, st == 2u);
            unsigned zm = __ballot_sync(FULLM, st == 0u);
            if (pm) {
                int fp = __ffs(pm) - 1;
                if ((zm & ((1u << fp) - 1u)) == 0) {
                    int c = (lane <= fp) ? (int)(w >> 2) : 0;
                    #pragma unroll
                    for (int off = 16; off; off >>= 1)
                        c += __shfl_xor_sync(FULLM, c, off);
                    prefix += c;
                    break;
                }
            } else if (zm == 0) {
                int c = (int)(w >> 2);
                #pragma unroll
                for (int off = 16; off; off >>= 1)
                    c += __shfl_xor_sync(FULLM, c, off);
                prefix += c;
                base -= 32;
            }
        }
        if (lane == 0) {
            s_prefix = prefix;
            atomicExch(&g_flags[b], (((unsigned)(prefix + block_tot)) << 2) | 2u);
        }
    }
    __syncthreads();

    if (i < NN) {
        g_rowptr[i] = s_prefix + incl - v;
        g_dinv[i]   = rsqrtf((float)(v + 1));
    }
    if (b == SCAN_B - 1 && tid == SCAN_T - 1) g_rowptr[NN] = EE;
}

// scatter with precomputed ranks: no atomics
__global__ void k_scatter(const int* __restrict__ ei) {
    int i = blockIdx.x * blockDim.x + threadIdx.x;
    if (i < EE / 4) {
        int4 s = ((const int4*)ei)[i];
        int4 d = ((const int4*)(ei + EE))[i];
        int4 r = ((const int4*)g_rank)[i];
        g_col[g_rowptr[d.x] + r.x] = s.x;
        g_col[g_rowptr[d.y] + r.y] = s.y;
        g_col[g_rowptr[d.z] + r.z] = s.z;
        g_col[g_rowptr[d.w] + r.w] = s.w;
    }
}

// ---------------- layer-1 dense GEMM: g_f1 = dinv * (x @ W1) ----------------
// Warp-cooperative split-K: lane l owns k in {4l..4l+3} (j=0) and {128+4l..+3} (j=1).
// 4 rows per iteration share each swizzled W LDS.128. Butterfly reduction.
// W smem swizzle: chunk c of row k stored at slot c ^ ((k>>2)&3);
// row base address (k<<6) XOR (((k>>4)&1)<<6). Conflict-free per 8-lane phase.

__device__ __forceinline__ void gemm1_reduce_store(unsigned long long L[8],
                                                   int lane, int row) {
    // round 1 (xor 16): keep 4 u64 (bit4 clear -> cols 0-7)
    unsigned long long K[4];
    #pragma unroll
    for (int i = 0; i < 4; i++) {
        unsigned long long snd = (lane & 16) ? L[i] : L[i + 4];
        unsigned long long rcv = __shfl_xor_sync(FULLM, snd, 16);
        unsigned long long kp  = (lane & 16) ? L[i + 4] : L[i];
        FADD2(K[i], kp, rcv);
    }
    // round 2 (xor 8)
    unsigned long long M[2];
    #pragma unroll
    for (int i = 0; i < 2; i++) {
        unsigned long long snd = (lane & 8) ? K[i] : K[i + 2];
        unsigned long long rcv = __shfl_xor_sync(FULLM, snd, 8);
        unsigned long long kp  = (lane & 8) ? K[i + 2] : K[i];
        FADD2(M[i], kp, rcv);
    }
    // round 3 (xor 4)
    unsigned long long P;
    {
        unsigned long long snd = (lane & 4) ? M[0] : M[1];
        unsigned long long rcv = __shfl_xor_sync(FULLM, snd, 4);
        unsigned long long kp  = (lane & 4) ? M[1] : M[0];
        FADD2(P, kp, rcv);
    }
    // round 4 (xor 2): split to scalar
    float lo, hi;
    UNPACK2(lo, hi, P);
    float snd = (lane & 2) ? lo : hi;
    float rcv = __shfl_xor_sync(FULLM, snd, 2);
    float val = ((lane & 2) ? hi : lo) + rcv;
    // round 5 (xor 1)
    val += __shfl_xor_sync(FULLM, val, 1);

    float dv = g_dinv[row];
    if (!(lane & 1))
        ((float*)g_f1)[(size_t)row * HID + (lane >> 1)] = val * dv;
}

__global__ void __launch_bounds__(256) k_gemm1(const float* __restrict__ x,
                                               const float* __restrict__ W1) {
    __shared__ __align__(16) char Ws[FIN * HID * 4];       // 16 KB, swizzled
    for (int g = threadIdx.x; g < FIN * HID / 4; g += blockDim.x) {
        int k = g >> 2, c = g & 3;
        float4 v = __ldg(&((const float4*)W1)[g]);
        unsigned addr = ((unsigned)(k << 6) ^ ((unsigned)((k >> 4) & 1) << 6))
                      + ((unsigned)(c ^ ((k >> 2) & 3)) << 4);
        *(float4*)(Ws + addr) = v;
    }
    __syncthreads();

    int lane = threadIdx.x & 31;
    int gw   = blockIdx.x * (blockDim.x >> 5) + (threadIdx.x >> 5);
    int row0 = gw * 16;
    if (row0 >= NN) return;                                // NN = 6250*16: warps all-or-nothing

    int m = lane & 3;
    int bb = (lane >> 2) & 1;
    const char* wbase = Ws + lane * 256;
    unsigned ccoff[4], choff[4];
    #pragma unroll
    for (int cc = 0; cc < 4; cc++) ccoff[cc] = (unsigned)((cc ^ bb) << 6);
    #pragma unroll
    for (int c = 0; c < 4; c++)  choff[c] = (unsigned)((c ^ m) << 4);

    #pragma unroll 1
    for (int q = 0; q < 4; q++) {                          // 4 quads of rows
        int ra = row0 + q * 4;
        unsigned long long acc[4][8];
        #pragma unroll
        for (int r = 0; r < 4; r++)
            #pragma unroll
            for (int i = 0; i < 8; i++) acc[r][i] = 0ull;

        #pragma unroll
        for (int j = 0; j < 2; j++) {
            float4 xv[4];
            #pragma unroll
            for (int r = 0; r < 4; r++)
                xv[r] = __ldg((const float4*)(x + (size_t)(ra + r) * FIN + j * 128 + lane * 4));

            const char* jb = wbase + j * 8192;
            #pragma unroll
            for (int cc = 0; cc < 4; cc++) {
                unsigned long long xp[4];
                #pragma unroll
                for (int r = 0; r < 4; r++) {
                    float f = (cc == 0) ? xv[r].x : (cc == 1) ? xv[r].y
                            : (cc == 2) ? xv[r].z : xv[r].w;
                    PACK2(xp[r], f);
                }
                const char* rp = jb + ccoff[cc];
                #pragma unroll
                for (int c = 0; c < 4; c++) {
                    ulonglong2 w = *(const ulonglong2*)(rp + choff[c]);
                    #pragma unroll
                    for (int r = 0; r < 4; r++) {
                        FFMA2(acc[r][2 * c],     xp[r], w.x);
                        FFMA2(acc[r][2 * c + 1], xp[r], w.y);
                    }
                }
            }
        }
        #pragma unroll
        for (int r = 0; r < 4; r++)
            gemm1_reduce_store(acc[r], lane, ra + r);
    }
}

// -------- shared 16-dim CSR gather: quad-per-edge, float4 loads -------------
__device__ __forceinline__ float4 warp_gather16(const float4* __restrict__ feat,
                                                int node, int lane) {
    int start = g_rowptr[node];
    int cnt   = g_rowptr[node + 1] - start;
    int q     = lane >> 2;
    int fs    = lane & 3;

    float4 acc = make_float4(0.f, 0.f, 0.f, 0.f);
    for (int base = 0; base < cnt; base += 32) {
        int t    = base + lane;
        int cidx = (t < cnt) ? g_col[start + t] : 0;
        int mm   = min(32, cnt - base);
        for (int j = 0; j < mm; j += 8) {
            int src = __shfl_sync(FULLM, cidx, j + q);
            if (j + q < mm) {
                float4 v = feat[(size_t)src * 4 + fs];
                acc.x += v.x; acc.y += v.y; acc.z += v.z; acc.w += v.w;
            }
        }
    }
    #pragma unroll
    for (int off = 4; off <= 16; off <<= 1) {
        acc.x += __shfl_xor_sync(FULLM, acc.x, off);
        acc.y += __shfl_xor_sync(FULLM, acc.y, off);
        acc.z += __shfl_xor_sync(FULLM, acc.z, off);
        acc.w += __shfl_xor_sync(FULLM, acc.w, off);
    }
    float4 sv = feat[(size_t)node * 4 + fs];
    acc.x += sv.x; acc.y += sv.y; acc.z += sv.z; acc.w += sv.w;
    return acc;
}

// -------- layer-1 aggregation + relu: g_f2 = dinv * relu(dinv*agg + b1) -----
__global__ void k_agg1(const float* __restrict__ b1) {
    __shared__ __align__(16) float b1s[HID];
    if (threadIdx.x < HID) b1s[threadIdx.x] = b1[threadIdx.x];
    __syncthreads();

    int lane = threadIdx.x & 31;
    int node = blockIdx.x * (blockDim.x >> 5) + (threadIdx.x >> 5);
    if (node >= NN) return;

    float4 acc = warp_gather16(g_f1, node, lane);

    float dv = g_dinv[node];
    float4 bv = ((const float4*)b1s)[lane & 3];
    float4 h;
    h.x = fmaxf(dv * acc.x + bv.x, 0.f) * dv;
    h.y = fmaxf(dv * acc.y + bv.y, 0.f) * dv;
    h.z = fmaxf(dv * acc.z + bv.z, 0.f) * dv;
    h.w = fmaxf(dv * acc.w + bv.w, 0.f) * dv;

    if (lane < 4) g_f2[(size_t)node * 4 + lane] = h;
}

// -------- layer-2 aggregation + fused 16x40 GEMM + log_softmax --------------
__global__ void k_agg2(const float* __restrict__ W2, const float* __restrict__ b2,
                       float* __restrict__ out) {
    __shared__ float W2s[HID * 64];
    __shared__ float b2s[CC];
    for (int i = threadIdx.x; i < HID * 64; i += blockDim.x) W2s[i] = 0.f;
    __syncthreads();
    for (int i = threadIdx.x; i < HID * CC; i += blockDim.x) {
        int k = i / CC, c = i % CC;
        W2s[k * 64 + c] = W2[i];
    }
    if (threadIdx.x < CC) b2s[threadIdx.x] = b2[threadIdx.x];
    __syncthreads();

    int lane = threadIdx.x & 31;
    int node = blockIdx.x * (blockDim.x >> 5) + (threadIdx.x >> 5);
    if (node >= NN) return;

    float4 acc = warp_gather16(g_f2, node, lane);

    float v0 = 0.f, v1 = 0.f;
    #pragma unroll
    for (int k = 0; k < HID; k++) {
        float comp = ((k & 3) == 0) ? acc.x : ((k & 3) == 1) ? acc.y
                   : ((k & 3) == 2) ? acc.z : acc.w;
        float tk = __shfl_sync(FULLM, comp, k >> 2);
        v0 += tk * W2s[k * 64 + lane];
        v1 += tk * W2s[k * 64 + 32 + lane];
    }

    float dv = g_dinv[node];
    float l0 = dv * v0 + b2s[lane];
    float l1 = (lane < 8) ? (dv * v1 + b2s[32 + lane]) : -3.4e38f;

    float M = fmaxf(l0, l1);
    #pragma unroll
    for (int off = 16; off > 0; off >>= 1)
        M = fmaxf(M, __shfl_xor_sync(FULLM, M, off));

    float se = expf(l0 - M) + ((lane < 8) ? expf(l1 - M) : 0.f);
    #pragma unroll
    for (int off = 16; off > 0; off >>= 1)
        se += __shfl_xor_sync(FULLM, se, off);

    float L = logf(se);
    out[(size_t)node * CC + lane] = l0 - M - L;
    if (lane < 8) out[(size_t)node * CC + 32 + lane] = l1 - M - L;
}

// ---------------- launch ----------------------------------------------------
extern "C" void kernel_launch(void* const* d_in, const int* in_sizes, int n_in,
                              void* d_out, int out_size) {
    const float* x  = (const float*)d_in[0];
    const int*   ei = (const int*)d_in[1];     // int32 edge index
    const float* W1 = (const float*)d_in[2];
    const float* b1 = (const float*)d_in[3];
    const float* W2 = (const float*)d_in[4];
    const float* b2 = (const float*)d_in[5];
    float*       out = (float*)d_out;

    static cudaStream_t s1 = nullptr;
    static cudaEvent_t  ev_fork = nullptr, ev_join = nullptr;
    if (!s1) {
        cudaStreamCreateWithFlags(&s1, cudaStreamNonBlocking);
        cudaEventCreateWithFlags(&ev_fork, cudaEventDisableTiming);
        cudaEventCreateWithFlags(&ev_join, cudaEventDisableTiming);
    }

    const int E4B = (EE / 4 + 255) / 256;   // 3125
    const int NB  = (NN + 255) / 256;       // 391
    const int GB  = (NN + 16 * 8 - 1) / (16 * 8);  // 782 blocks, 16 rows/warp

    k_zero<<<NB, 256>>>();
    k_hist<<<E4B, 256>>>(ei);
    k_scan<<<SCAN_B, SCAN_T>>>();           // rowptr + dinv ready here

    // fork: gemm1 (needs only dinv) overlaps scatter
    cudaEventRecord(ev_fork, 0);
    cudaStreamWaitEvent(s1, ev_fork, 0);
    k_gemm1<<<GB, 256, 0, s1>>>(x, W1);
    cudaEventRecord(ev_join, s1);

    k_scatter<<<E4B, 256>>>(ei);

    cudaStreamWaitEvent(0, ev_join, 0);
    k_agg1<<<(NN + 7) / 8, 256>>>(b1);
    k_agg2<<<(NN + 7) / 8, 256>>>(W2, b2, out);
}

// round 9
// speedup vs baseline: 1.0887x; 1.0887x over previous
#include <cuda_runtime.h>
#include <math.h>

#define NN   100000
#define EE   3200000
#define FIN  256
#define HID  16
#define CC   40
#define FULLM 0xffffffffu

#define SCAN_T 512
#define SCAN_B ((NN + SCAN_T - 1) / SCAN_T)   // 196

// ---------------- scratch (device globals; no allocation allowed) ------------
__device__ int      g_rowptr[NN + 1];
__device__ int      g_fill[NN];
__device__ int      g_rank[EE];
__device__ int      g_col[EE];
__device__ float    g_dinv[NN];
__device__ float4   g_f1[NN * 4];   // dinv * (x @ W1), 16 floats/node
__device__ float4   g_f2[NN * 4];   // dinv * relu(h1), 16 floats/node
__device__ unsigned g_flags[SCAN_B];  // decoupled-lookback state: (val<<2)|st

#define FFMA2(d, a, b) asm("fma.rn.f32x2 %0, %1, %2, %0;" : "+l"(d) : "l"(a), "l"(b))
#define FADD2(d, a, b) asm("add.rn.f32x2 %0, %1, %2;" : "=l"(d) : "l"(a), "l"(b))
#define PACK2(d, f)    asm("mov.b64 %0, {%1, %1};" : "=l"(d) : "f"(f))
#define UNPACK2(lo, hi, v) asm("mov.b64 {%0, %1}, %2;" : "=f"(lo), "=f"(hi) : "l"(v))

// ---------------- CSR build -------------------------------------------------
__global__ void k_zero() {
    int i = blockIdx.x * blockDim.x + threadIdx.x;
    if (i < NN) g_fill[i] = 0;
    if (i < SCAN_B) g_flags[i] = 0u;
}

// histogram + per-edge within-bucket rank (atomic return value)
__global__ void k_hist(const int* __restrict__ ei) {
    int i = blockIdx.x * blockDim.x + threadIdx.x;
    if (i < EE / 4) {
        int4 d = ((const int4*)(ei + EE))[i];
        int4 r;
        r.x = atomicAdd(&g_fill[d.x], 1);
        r.y = atomicAdd(&g_fill[d.y], 1);
        r.z = atomicAdd(&g_fill[d.z], 1);
        r.w = atomicAdd(&g_fill[d.w], 1);
        ((int4*)g_rank)[i] = r;
    }
}

// single-pass exclusive scan of g_fill -> g_rowptr, plus dinv. Decoupled lookback.
__global__ void k_scan() {
    __shared__ int wt[SCAN_T / 32];
    __shared__ int s_prefix;
    int tid = threadIdx.x, lane = tid & 31, wid = tid >> 5, b = blockIdx.x;
    int i = b * SCAN_T + tid;
    int v = (i < NN) ? g_fill[i] : 0;

    int x = v;
    #pragma unroll
    for (int off = 1; off < 32; off <<= 1) {
        int t = __shfl_up_sync(FULLM, x, off);
        if (lane >= off) x += t;
    }
    if (lane == 31) wt[wid] = x;
    __syncthreads();
    if (wid == 0) {
        int w = (lane < SCAN_T / 32) ? wt[lane] : 0;
        #pragma unroll
        for (int off = 1; off < SCAN_T / 32; off <<= 1) {
            int t = __shfl_up_sync(FULLM, w, off);
            if (lane >= off) w += t;
        }
        if (lane < SCAN_T / 32) wt[lane] = w;
    }
    __syncthreads();
    int block_tot = wt[SCAN_T / 32 - 1];
    int incl = ((wid == 0) ? 0 : wt[wid - 1]) + x;

    if (tid == 0) {
        unsigned pub = (b == 0) ? (((unsigned)block_tot << 2) | 2u)
                                : (((unsigned)block_tot << 2) | 1u);
        atomicExch(&g_flags[b], pub);
    }

    if (b == 0) {
        if (tid == 0) s_prefix = 0;
    } else if (wid == 0) {
        int prefix = 0;
        int base = b - 1;
        while (true) {
            int idx = base - lane;
            unsigned w = (idx >= 0) ? *((volatile unsigned*)&g_flags[idx]) : 2u;
            unsigned st = w & 3u;
            unsigned pm = __ballot_sync(FULLM, st == 2u);
            unsigned zm = __ballot_sync(FULLM, st == 0u);
            if (pm) {
                int fp = __ffs(pm) - 1;
                if ((zm & ((1u << fp) - 1u)) == 0) {
                    int c = (lane <= fp) ? (int)(w >> 2) : 0;
                    #pragma unroll
                    for (int off = 16; off; off >>= 1)
                        c += __shfl_xor_sync(FULLM, c, off);
                    prefix += c;
                    break;
                }
            } else if (zm == 0) {
                int c = (int)(w >> 2);
                #pragma unroll
                for (int off = 16; off; off >>= 1)
                    c += __shfl_xor_sync(FULLM, c, off);
                prefix += c;
                base -= 32;
            }
        }
        if (lane == 0) {
            s_prefix = prefix;
            atomicExch(&g_flags[b], (((unsigned)(prefix + block_tot)) << 2) | 2u);
        }
    }
    __syncthreads();

    if (i < NN) {
        g_rowptr[i] = s_prefix + incl - v;
        g_dinv[i]   = rsqrtf((float)(v + 1));
    }
    if (b == SCAN_B - 1 && tid == SCAN_T - 1) g_rowptr[NN] = EE;
}

// scatter with precomputed ranks: no atomics
__global__ void k_scatter(const int* __restrict__ ei) {
    int i = blockIdx.x * blockDim.x + threadIdx.x;
    if (i < EE / 4) {
        int4 s = ((const int4*)ei)[i];
        int4 d = ((const int4*)(ei + EE))[i];
        int4 r = ((const int4*)g_rank)[i];
        g_col[g_rowptr[d.x] + r.x] = s.x;
        g_col[g_rowptr[d.y] + r.y] = s.y;
        g_col[g_rowptr[d.z] + r.z] = s.z;
        g_col[g_rowptr[d.w] + r.w] = s.w;
    }
}

// ---------------- layer-1 dense GEMM: g_f1 = dinv * (x @ W1) ----------------
// Column-split warp-cooperative scheme ("D2"):
//   lane l -> pair q2 = l>>1, parity p = l&1.
//   Lane owns cols [8p, 8p+8) and k in {8*q2..+8} u {128+8*q2..+8}  (16 k total).
//   acc = 4 u64 (f32x2 col pairs) per row, 4 rows/iter -> 16 u64 = 32 regs.
//   x float4 loads coalesced (lane*16B); pair lanes swap via shfl_xor(.,1).
//   W smem swizzle (conflict-free LDS.128, verified per 8-lane phase):
//     chunk ch of row k stored at word  (k*16 ^ (((k>>4)&1)<<4)) + 4*((ch^(k>>3))&3)

__global__ void __launch_bounds__(128, 5) k_gemm1(const float* __restrict__ x,
                                                  const float* __restrict__ W1) {
    __shared__ __align__(16) float Ws[FIN * HID];          // 16 KB, swizzled
    for (int g = threadIdx.x; g < FIN * HID / 4; g += blockDim.x) {
        int k = g >> 2, ch = g & 3;
        float4 v = __ldg(&((const float4*)W1)[g]);
        unsigned word = ((unsigned)(k * 16) ^ (((unsigned)(k >> 4) & 1u) << 4))
                      + (((unsigned)(ch ^ (k >> 3)) & 3u) << 2);
        *(float4*)&Ws[word] = v;
    }
    __syncthreads();

    int lane = threadIdx.x & 31;
    int gw   = blockIdx.x * 4 + (threadIdx.x >> 5);
    int row0 = gw << 4;                                    // 16 rows per warp
    if (row0 >= NN) return;                                // NN = 6250*16: all-or-nothing

    int q2 = lane >> 1;
    int p  = lane & 1;
    unsigned sw   = (((unsigned)q2 >> 1) & 1u) << 6;       // byte offset XOR
    unsigned cho0 = (((unsigned)((2 * p)     ^ (q2 & 3))) & 3u) << 4;
    unsigned cho1 = (((unsigned)((2 * p + 1) ^ (q2 & 3))) & 3u) << 4;
    unsigned kbase = (unsigned)q2 << 9;                    // (8*q2)<<6 bytes
    // output column for this lane after the split-reduction (lanes 0-15 store)
    int ocol = ((lane & 1) << 3) | (((lane >> 1) & 1) << 2)
             | (((lane >> 2) & 1) << 1) | ((lane >> 3) & 1);

    const char* WsB = (const char*)Ws;

    #pragma unroll 1
    for (int q = 0; q < 4; q++) {
        int ra = row0 + q * 4;
        unsigned long long acc[4][4];
        #pragma unroll
        for (int r = 0; r < 4; r++)
            #pragma unroll
            for (int u = 0; u < 4; u++) acc[r][u] = 0ull;

        #pragma unroll
        for (int j = 0; j < 2; j++) {
            float4 own[4], oth[4];
            #pragma unroll
            for (int r = 0; r < 4; r++)
                own[r] = __ldg((const float4*)(x + (size_t)(ra + r) * FIN + j * 128 + lane * 4));
            #pragma unroll
            for (int r = 0; r < 4; r++) {
                oth[r].x = __shfl_xor_sync(FULLM, own[r].x, 1);
                oth[r].y = __shfl_xor_sync(FULLM, own[r].y, 1);
                oth[r].z = __shfl_xor_sync(FULLM, own[r].z, 1);
                oth[r].w = __shfl_xor_sync(FULLM, own[r].w, 1);
            }
            // chunkA (k = 8*q2+0..3): even lane -> own, odd -> oth
            // chunkB (k = 8*q2+4..7): even lane -> oth, odd -> own
            #pragma unroll
            for (int kk = 0; kk < 8; kk++) {
                unsigned off = (kbase + (unsigned)(j * 8192 + kk * 64)) ^ sw;
                ulonglong2 w0 = *(const ulonglong2*)(WsB + off + cho0);
                ulonglong2 w1 = *(const ulonglong2*)(WsB + off + cho1);
                #pragma unroll
                for (int r = 0; r < 4; r++) {
                    float f;
                    if (kk < 4) {
                        float4 s = p ? oth[r] : own[r];
                        f = (kk == 0) ? s.x : (kk == 1) ? s.y : (kk == 2) ? s.z : s.w;
                    } else {
                        float4 s = p ? own[r] : oth[r];
                        f = (kk == 4) ? s.x : (kk == 5) ? s.y : (kk == 6) ? s.z : s.w;
                    }
                    unsigned long long xp;
                    PACK2(xp, f);
                    FFMA2(acc[r][0], xp, w0.x);
                    FFMA2(acc[r][1], xp, w0.y);
                    FFMA2(acc[r][2], xp, w1.x);
                    FFMA2(acc[r][3], xp, w1.y);
                }
            }
        }

        // column-splitting butterfly: xor 2, 4, 8 (u64 rounds), then scalar xor 16
        #pragma unroll
        for (int r = 0; r < 4; r++) {
            unsigned long long h0, h1, P;
            {
                unsigned long long s0 = (lane & 2) ? acc[r][0] : acc[r][2];
                unsigned long long s1 = (lane & 2) ? acc[r][1] : acc[r][3];
                unsigned long long r0 = __shfl_xor_sync(FULLM, s0, 2);
                unsigned long long r1 = __shfl_xor_sync(FULLM, s1, 2);
                unsigned long long k0 = (lane & 2) ? acc[r][2] : acc[r][0];
                unsigned long long k1 = (lane & 2) ? acc[r][3] : acc[r][1];
                FADD2(h0, k0, r0);
                FADD2(h1, k1, r1);
            }
            {
                unsigned long long s = (lane & 4) ? h0 : h1;
                unsigned long long rc = __shfl_xor_sync(FULLM, s, 4);
                unsigned long long kp = (lane & 4) ? h1 : h0;
                FADD2(P, kp, rc);
            }
            float lo, hi;
            UNPACK2(lo, hi, P);
            float snd = (lane & 8) ? lo : hi;
            float rcv = __shfl_xor_sync(FULLM, snd, 8);
            float val = ((lane & 8) ? hi : lo) + rcv;
            val += __shfl_xor_sync(FULLM, val, 16);

            if (lane < 16) {
                float dv = g_dinv[ra + r];
                ((float*)g_f1)[(size_t)(ra + r) * HID + ocol] = val * dv;
            }
        }
    }
}

// -------- shared 16-dim CSR gather: quad-per-edge, float4 loads -------------
__device__ __forceinline__ float4 warp_gather16(const float4* __restrict__ feat,
                                                int node, int lane) {
    int start = g_rowptr[node];
    int cnt   = g_rowptr[node + 1] - start;
    int q     = lane >> 2;
    int fs    = lane & 3;

    float4 acc = make_float4(0.f, 0.f, 0.f, 0.f);
    for (int base = 0; base < cnt; base += 32) {
        int t    = base + lane;
        int cidx = (t < cnt) ? g_col[start + t] : 0;
        int mm   = min(32, cnt - base);
        for (int j = 0; j < mm; j += 8) {
            int src = __shfl_sync(FULLM, cidx, j + q);
            if (j + q < mm) {
                float4 v = feat[(size_t)src * 4 + fs];
                acc.x += v.x; acc.y += v.y; acc.z += v.z; acc.w += v.w;
            }
        }
    }
    #pragma unroll
    for (int off = 4; off <= 16; off <<= 1) {
        acc.x += __shfl_xor_sync(FULLM, acc.x, off);
        acc.y += __shfl_xor_sync(FULLM, acc.y, off);
        acc.z += __shfl_xor_sync(FULLM, acc.z, off);
        acc.w += __shfl_xor_sync(FULLM, acc.w, off);
    }
    float4 sv = feat[(size_t)node * 4 + fs];
    acc.x += sv.x; acc.y += sv.y; acc.z += sv.z; acc.w += sv.w;
    return acc;
}

// -------- layer-1 aggregation + relu: g_f2 = dinv * relu(dinv*agg + b1) -----
__global__ void k_agg1(const float* __restrict__ b1) {
    __shared__ __align__(16) float b1s[HID];
    if (threadIdx.x < HID) b1s[threadIdx.x] = b1[threadIdx.x];
    __syncthreads();

    int lane = threadIdx.x & 31;
    int node = blockIdx.x * (blockDim.x >> 5) + (threadIdx.x >> 5);
    if (node >= NN) return;

    float4 acc = warp_gather16(g_f1, node, lane);

    float dv = g_dinv[node];
    float4 bv = ((const float4*)b1s)[lane & 3];
    float4 h;
    h.x = fmaxf(dv * acc.x + bv.x, 0.f) * dv;
    h.y = fmaxf(dv * acc.y + bv.y, 0.f) * dv;
    h.z = fmaxf(dv * acc.z + bv.z, 0.f) * dv;
    h.w = fmaxf(dv * acc.w + bv.w, 0.f) * dv;

    if (lane < 4) g_f2[(size_t)node * 4 + lane] = h;
}

// -------- layer-2 aggregation + fused 16x40 GEMM + log_softmax --------------
__global__ void k_agg2(const float* __restrict__ W2, const float* __restrict__ b2,
                       float* __restrict__ out) {
    __shared__ float W2s[HID * 64];
    __shared__ float b2s[CC];
    for (int i = threadIdx.x; i < HID * 64; i += blockDim.x) W2s[i] = 0.f;
    __syncthreads();
    for (int i = threadIdx.x; i < HID * CC; i += blockDim.x) {
        int k = i / CC, c = i % CC;
        W2s[k * 64 + c] = W2[i];
    }
    if (threadIdx.x < CC) b2s[threadIdx.x] = b2[threadIdx.x];
    __syncthreads();

    int lane = threadIdx.x & 31;
    int node = blockIdx.x * (blockDim.x >> 5) + (threadIdx.x >> 5);
    if (node >= NN) return;

    float4 acc = warp_gather16(g_f2, node, lane);

    float v0 = 0.f, v1 = 0.f;
    #pragma unroll
    for (int k = 0; k < HID; k++) {
        float comp = ((k & 3) == 0) ? acc.x : ((k & 3) == 1) ? acc.y
                   : ((k & 3) == 2) ? acc.z : acc.w;
        float tk = __shfl_sync(FULLM, comp, k >> 2);
        v0 += tk * W2s[k * 64 + lane];
        v1 += tk * W2s[k * 64 + 32 + lane];
    }

    float dv = g_dinv[node];
    float l0 = dv * v0 + b2s[lane];
    float l1 = (lane < 8) ? (dv * v1 + b2s[32 + lane]) : -3.4e38f;

    float M = fmaxf(l0, l1);
    #pragma unroll
    for (int off = 16; off > 0; off >>= 1)
        M = fmaxf(M, __shfl_xor_sync(FULLM, M, off));

    float se = expf(l0 - M) + ((lane < 8) ? expf(l1 - M) : 0.f);
    #pragma unroll
    for (int off = 16; off > 0; off >>= 1)
        se += __shfl_xor_sync(FULLM, se, off);

    float L = logf(se);
    out[(size_t)node * CC + lane] = l0 - M - L;
    if (lane < 8) out[(size_t)node * CC + 32 + lane] = l1 - M - L;
}

// ---------------- launch ----------------------------------------------------
extern "C" void kernel_launch(void* const* d_in, const int* in_sizes, int n_in,
                              void* d_out, int out_size) {
    const float* x  = (const float*)d_in[0];
    const int*   ei = (const int*)d_in[1];     // int32 edge index
    const float* W1 = (const float*)d_in[2];
    const float* b1 = (const float*)d_in[3];
    const float* W2 = (const float*)d_in[4];
    const float* b2 = (const float*)d_in[5];
    float*       out = (float*)d_out;

    static cudaStream_t s1 = nullptr;
    static cudaEvent_t  ev_fork = nullptr, ev_join = nullptr;
    if (!s1) {
        cudaStreamCreateWithFlags(&s1, cudaStreamNonBlocking);
        cudaEventCreateWithFlags(&ev_fork, cudaEventDisableTiming);
        cudaEventCreateWithFlags(&ev_join, cudaEventDisableTiming);
    }

    const int E4B = (EE / 4 + 255) / 256;   // 3125
    const int NB  = (NN + 255) / 256;       // 391
    const int GB  = (NN / 16 + 3) / 4;      // 1563 blocks, 4 warps x 16 rows

    k_zero<<<NB, 256>>>();
    k_hist<<<E4B, 256>>>(ei);
    k_scan<<<SCAN_B, SCAN_T>>>();           // rowptr + dinv ready here

    // fork: gemm1 (needs only dinv) overlaps scatter
    cudaEventRecord(ev_fork, 0);
    cudaStreamWaitEvent(s1, ev_fork, 0);
    k_gemm1<<<GB, 128, 0, s1>>>(x, W1);
    cudaEventRecord(ev_join, s1);

    k_scatter<<<E4B, 256>>>(ei);

    cudaStreamWaitEvent(0, ev_join, 0);
    k_agg1<<<(NN + 7) / 8, 256>>>(b1);
    k_agg2<<<(NN + 7) / 8, 256>>>(W2, b2, out);
}